// round 2
// baseline (speedup 1.0000x reference)
#include <cuda_runtime.h>
#include <cuda_bf16.h>
#include <cstdint>

#define V 50000
#define BDIM 4
#define CIN 128
#define COUT 128
#define KCHEB 4
#define FDIM 512              // B*Cin
#define EMAX 800000

// ---------------- scratch (device globals; allocation-free rule) -------------
// Single 4-buffer array; kernels index it in DEVICE code only (never pass the
// symbol from host — host sees only the shadow address).
__device__ float g_x[KCHEB][(size_t)V * FDIM];

__device__ int   g_hist[V];
__device__ int   g_rowptr[V + 1];
__device__ int   g_cursor[V];
__device__ int   g_col[EMAX];
__device__ float g_val[EMAX];

// ---------------- CSR build --------------------------------------------------
__global__ void zero_hist_kernel() {
    int i = blockIdx.x * blockDim.x + threadIdx.x;
    if (i < V) g_hist[i] = 0;
}

__global__ void hist_kernel(const int* __restrict__ row, int E) {
    int i = blockIdx.x * blockDim.x + threadIdx.x;
    if (i < E) atomicAdd(&g_hist[row[i]], 1);
}

// single-block inclusive scan over 50000 counters -> rowptr + cursor
__global__ void scan_kernel() {
    __shared__ int sdata[1024];
    __shared__ int s_carry;
    int tid = threadIdx.x;
    if (tid == 0) { s_carry = 0; g_rowptr[0] = 0; }
    __syncthreads();
    for (int base = 0; base < V; base += 1024) {
        int i = base + tid;
        int val = (i < V) ? g_hist[i] : 0;
        sdata[tid] = val;
        __syncthreads();
        #pragma unroll
        for (int off = 1; off < 1024; off <<= 1) {
            int tmp = (tid >= off) ? sdata[tid - off] : 0;
            __syncthreads();
            sdata[tid] += tmp;
            __syncthreads();
        }
        int inc = sdata[tid] + s_carry;
        if (i < V) {
            g_rowptr[i + 1] = inc;
            g_cursor[i]     = inc - val;   // exclusive offset
        }
        __syncthreads();
        if (tid == 1023) s_carry = s_carry + sdata[1023];
        __syncthreads();
    }
}

__global__ void scatter_kernel(const int* __restrict__ row,
                               const int* __restrict__ col,
                               const float* __restrict__ val, int E) {
    int i = blockIdx.x * blockDim.x + threadIdx.x;
    if (i < E) {
        int r = row[i];
        int p = atomicAdd(&g_cursor[r], 1);
        g_col[p] = col[i];
        g_val[p] = val[i];
    }
}

// ---------------- transpose: x (B,Cin,V) -> g_x[0] (V, B*Cin) ----------------
__global__ void transpose_kernel(const float* __restrict__ x) {
    __shared__ float tile[32][33];
    int v0 = blockIdx.x * 32;
    int f0 = blockIdx.y * 32;
    int tx = threadIdx.x, ty = threadIdx.y;   // 32 x 8
    #pragma unroll
    for (int r = 0; r < 32; r += 8) {
        int f = f0 + ty + r;
        int v = v0 + tx;
        tile[ty + r][tx] = (v < V) ? x[(size_t)f * V + v] : 0.f;
    }
    __syncthreads();
    #pragma unroll
    for (int r = 0; r < 32; r += 8) {
        int v = v0 + ty + r;
        int f = f0 + tx;
        if (v < V) g_x[0][(size_t)v * FDIM + f] = tile[tx][ty + r];
    }
}

// ---------------- SpMM + Chebyshev combine -----------------------------------
// g_x[oi][r,:] = alpha * sum_e val[e]*g_x[ii][col[e],:]  + beta * g_x[pi][r,:]
// one warp per (row, 128-float chunk); lane handles a float4.
__global__ void spmm_cheb_kernel(int ii, int pi, int oi,
                                 float alpha, float beta) {
    const float* __restrict__ xin   = &g_x[ii][0];
    const float* __restrict__ xprev = &g_x[pi][0];
    float*       __restrict__ xout  = &g_x[oi][0];

    int gw   = (blockIdx.x * blockDim.x + threadIdx.x) >> 5;
    int lane = threadIdx.x & 31;
    int r  = gw >> 2;
    int ch = gw & 3;
    if (r >= V) return;
    int fo = ch * 128 + (lane << 2);

    int e0 = g_rowptr[r];
    int e1 = g_rowptr[r + 1];

    float4 s = make_float4(0.f, 0.f, 0.f, 0.f);
    for (int e = e0; e < e1; e++) {
        int   c = g_col[e];
        float w = g_val[e];
        float4 xv = *(const float4*)(xin + (size_t)c * FDIM + fo);
        s.x += w * xv.x; s.y += w * xv.y; s.z += w * xv.z; s.w += w * xv.w;
    }
    float4 o;
    if (beta != 0.f) {
        float4 p = *(const float4*)(xprev + (size_t)r * FDIM + fo);
        o.x = alpha * s.x + beta * p.x;
        o.y = alpha * s.y + beta * p.y;
        o.z = alpha * s.z + beta * p.z;
        o.w = alpha * s.w + beta * p.w;
    } else {
        o.x = alpha * s.x; o.y = alpha * s.y; o.z = alpha * s.z; o.w = alpha * s.w;
    }
    *(float4*)(xout + (size_t)r * FDIM + fo) = o;
}

// ---------------- GEMM: out[b,o,v] = sum_{k,c} xk[v, b*128+c] * W[k,c,o] + bias
#define BM 64
#define BN 128
#define BK 16

__global__ void cheb_gemm_kernel(const float* __restrict__ W,
                                 const float* __restrict__ bias,
                                 float* __restrict__ out) {
    __shared__ float As[BK][BM];        // A^T tile
    __shared__ float Bs[BK][BN];
    __shared__ float Cs[BM][BN + 1];    // padded for conflict-free column read

    int b     = blockIdx.y;
    int vbase = blockIdx.x * BM;
    int t     = threadIdx.x;            // 256 threads
    int ot = t & 31;                    // o group (4 o's)
    int vt = t >> 5;                    // v group (8 v's)
    int o0 = ot * 4;
    int v0 = vt * 8;

    float acc[8][4];
    #pragma unroll
    for (int i = 0; i < 8; i++)
        #pragma unroll
        for (int j = 0; j < 4; j++) acc[i][j] = 0.f;

    for (int kb = 0; kb < KCHEB; kb++) {
        const float* __restrict__ A = &g_x[kb][0];
        for (int cc = 0; cc < CIN; cc += BK) {
            // ---- load A tile (64 v x 16 c), transposed into As[c][v]
            {
                int r = t >> 2;          // 0..63
                int q = t & 3;           // float4 slot
                int v = vbase + r;
                float4 g = make_float4(0.f, 0.f, 0.f, 0.f);
                if (v < V)
                    g = *(const float4*)(A + (size_t)v * FDIM + b * CIN + cc + q * 4);
                As[q * 4 + 0][r] = g.x;
                As[q * 4 + 1][r] = g.y;
                As[q * 4 + 2][r] = g.z;
                As[q * 4 + 3][r] = g.w;
            }
            // ---- load B tile (16 c x 128 o)
            #pragma unroll
            for (int s = 0; s < 2; s++) {
                int idx = t + s * 256;            // 0..511 float4s
                int rr  = idx >> 5;               // 0..15
                int oq  = (idx & 31) * 4;
                float4 g = *(const float4*)(W + ((size_t)(kb * CIN + cc + rr)) * COUT + oq);
                *(float4*)&Bs[rr][oq] = g;
            }
            __syncthreads();

            #pragma unroll
            for (int kk = 0; kk < BK; kk++) {
                float a[8], w[4];
                *(float4*)&a[0] = *(const float4*)&As[kk][v0];
                *(float4*)&a[4] = *(const float4*)&As[kk][v0 + 4];
                *(float4*)&w[0] = *(const float4*)&Bs[kk][o0];
                #pragma unroll
                for (int i = 0; i < 8; i++)
                    #pragma unroll
                    for (int j = 0; j < 4; j++)
                        acc[i][j] += a[i] * w[j];
            }
            __syncthreads();
        }
    }

    // ---- epilogue: stage in smem, store v-coalesced
    #pragma unroll
    for (int i = 0; i < 8; i++)
        #pragma unroll
        for (int j = 0; j < 4; j++)
            Cs[v0 + i][o0 + j] = acc[i][j];
    __syncthreads();

    for (int idx = t; idx < BM * BN; idx += 256) {
        int o  = idx >> 6;       // 0..127
        int v  = idx & 63;
        int gv = vbase + v;
        if (gv < V)
            out[((size_t)b * COUT + o) * V + gv] = Cs[v][o] + bias[o];
    }
}

// ---------------- launcher ----------------------------------------------------
extern "C" void kernel_launch(void* const* d_in, const int* in_sizes, int n_in,
                              void* d_out, int out_size) {
    const float* x        = (const float*)d_in[0];
    const int*   edge_row = (const int*)d_in[1];
    const int*   edge_col = (const int*)d_in[2];
    const float* edge_val = (const float*)d_in[3];
    const float* weights  = (const float*)d_in[4];
    const float* biases   = (const float*)d_in[5];
    float*       out      = (float*)d_out;

    int E = in_sizes[1];

    // CSR build
    zero_hist_kernel<<<(V + 255) / 256, 256>>>();
    hist_kernel<<<(E + 255) / 256, 256>>>(edge_row, E);
    scan_kernel<<<1, 1024>>>();
    scatter_kernel<<<(E + 255) / 256, 256>>>(edge_row, edge_col, edge_val, E);

    // transpose x -> g_x[0] (V, 512)
    {
        dim3 gb((V + 31) / 32, FDIM / 32);
        dim3 tb(32, 8);
        transpose_kernel<<<gb, tb>>>(x);
    }

    // Chebyshev recurrence (buffer indices resolved in device code)
    {
        int warps  = V * 4;
        int blocks = (warps * 32 + 255) / 256;
        spmm_cheb_kernel<<<blocks, 256>>>(0, 0, 1, 1.f, 0.f);
        spmm_cheb_kernel<<<blocks, 256>>>(1, 0, 2, 2.f, -1.f);
        spmm_cheb_kernel<<<blocks, 256>>>(2, 1, 3, 2.f, -1.f);
    }

    // fused GEMM + bias + output permute
    {
        dim3 gb((V + BM - 1) / BM, BDIM);
        cheb_gemm_kernel<<<gb, 256>>>(weights, biases, out);
    }
}